// round 15
// baseline (speedup 1.0000x reference)
#include <cuda_runtime.h>
#include <cuda_bf16.h>
#include <cuda_fp16.h>
#include <cstdint>

// ---------------------------------------------------------------------------
// GromovWassersteinEmbedding — GB300 sm_103a (target sm_103 => mma.sync path)
//
//   d_gw = f1·rs + f2·csm - 2*<T, Cs T Ct>
//   Cs = c0·J + diag(a) + As,  Ct = c0·J + diag(b) + Bs
//   <T,CsTCt> = c0²S² + c0·(rsᵀDs rs + csmᵀDt csm) + <T, Ds T Dt>
//     rank-one forms EXACT fp32 in cost kernels; residual via f16 mma.sync
//     GEMMs (f16 accum). R15: 512-thread GEMM CTAs (16 warps) to test the
//     occupancy axis; gather ∥ tpass; side stream hides cost1/d_w/orth.
//   X = Ds T = (As@T) descaled + diag(a)·T (fp32 epilogue), stored f16.
//   <T, Ds T Dt> = <T, X@Bs> + Σ_j xb[j]·db[j].
//   Scales: Ds,Dt ×1, T ×2^23, X ×2^27.
// ---------------------------------------------------------------------------

using bf16 = __nv_bfloat16;

constexpr int NV = 4096;
constexpr int DV = 128;
constexpr float C0F = 0.99326205f;
constexpr float SC_T = 8388608.f;          // 2^23
constexpr float SC_X = 134217728.f;        // 2^27
constexpr float INV_G1 = 1.f / SC_T;
constexpr double INV_G2 = 1.0 / (double)SC_X;

__device__ float   g_embs1[NV * DV];
__device__ float   g_embs2[NV * DV];
__device__ bf16    g_eh1[NV * DV];
__device__ bf16    g_eh2[NV * DV];
__device__ float   g_e1[NV];
__device__ float   g_e2[NV];
__device__ __half  g_csh[(size_t)NV * NV];
__device__ __half  g_cth[(size_t)NV * NV];
__device__ __half  g_Tth[(size_t)NV * NV];
__device__ __half  g_Xh [(size_t)NV * NV];
__device__ float   g_da[NV];
__device__ float   g_db[NV];
__device__ float   g_f1[NV];
__device__ float   g_f2[NV];
__device__ float   g_rs[NV];
__device__ float   g_csm[NV];
__device__ float   g_xb[NV];
__device__ float   g_orthG[2 * DV * DV];
__device__ double  g_acc[16];

// ------------------------------- helpers -----------------------------------
__device__ __forceinline__ uint32_t smem_u32(const void* p) {
    uint32_t a;
    asm("{ .reg .u64 t; cvta.to.shared.u64 t, %1; cvt.u32.u64 %0, t; }" : "=r"(a) : "l"(p));
    return a;
}
#define CP16(dst, src) \
    asm volatile("cp.async.cg.shared.global [%0], [%1], 16;" :: "r"(dst), "l"(src))
#define CP_COMMIT() asm volatile("cp.async.commit_group;" ::: "memory")
#define CP_WAIT3()  asm volatile("cp.async.wait_group 3;" ::: "memory")

__device__ __forceinline__ void mma_bf16(float c[4], const uint32_t a[4], const uint32_t b[2]) {
    asm volatile("mma.sync.aligned.m16n8k16.row.col.f32.bf16.bf16.f32 "
                 "{%0,%1,%2,%3}, {%4,%5,%6,%7}, {%8,%9}, {%0,%1,%2,%3};"
                 : "+f"(c[0]), "+f"(c[1]), "+f"(c[2]), "+f"(c[3])
                 : "r"(a[0]), "r"(a[1]), "r"(a[2]), "r"(a[3]),
                   "r"(b[0]), "r"(b[1]));
}
__device__ __forceinline__ void mma_f16h(uint32_t c[2], const uint32_t a[4], const uint32_t b[2]) {
    asm volatile("mma.sync.aligned.m16n8k16.row.col.f16.f16.f16.f16 "
                 "{%0,%1}, {%2,%3,%4,%5}, {%6,%7}, {%0,%1};"
                 : "+r"(c[0]), "+r"(c[1])
                 : "r"(a[0]), "r"(a[1]), "r"(a[2]), "r"(a[3]),
                   "r"(b[0]), "r"(b[1]));
}

// ---------------------------------------------------------------------------
__global__ void k_init() {
    int i = blockIdx.x * blockDim.x + threadIdx.x;
    if (i < 2 * DV * DV) g_orthG[i] = 0.f;
    if (i < NV) { g_f1[i] = 0.f; g_f2[i] = 0.f; g_csm[i] = 0.f; g_rs[i] = 0.f; g_xb[i] = 0.f; }
    if (i < 16) g_acc[i] = 0.0;
}

__global__ void k_gather(const int* __restrict__ idx1, const int* __restrict__ idx2,
                         const float* __restrict__ w1, const float* __restrict__ w2) {
    int b = blockIdx.x;
    int table = b >> 12;
    int row = b & (NV - 1);
    const int* __restrict__ idx = table ? idx2 : idx1;
    const float* __restrict__ w = table ? w2 : w1;
    float* embs = table ? g_embs2 : g_embs1;
    bf16* embh = table ? g_eh2 : g_eh1;
    float* e = table ? g_e2 : g_e1;
    int t = threadIdx.x;
    float v = w[(size_t)idx[row] * DV + t];
    embs[row * DV + t] = v;
    embh[row * DV + t] = __float2bfloat16(v);
    float s = v * v;
    #pragma unroll
    for (int o = 16; o; o >>= 1) s += __shfl_down_sync(0xffffffffu, s, o);
    __shared__ float ws[4];
    if ((t & 31) == 0) ws[t >> 5] = s;
    __syncthreads();
    if (t == 0) e[row] = sqrtf(ws[0] + ws[1] + ws[2] + ws[3]);
}

// Fused T pass: rowsum + colsum + transposed f16 quantization.
__global__ void k_tpass(const float* __restrict__ T) {
    __shared__ float tile[32][33];
    __shared__ float colp[256];
    int x0 = blockIdx.x * 32, y0 = blockIdx.y * 32;
    int tx = threadIdx.x, ty = threadIdx.y;
    float v[4];
    #pragma unroll
    for (int j = 0; j < 4; j++) {
        v[j] = T[(size_t)(y0 + ty + 8 * j) * NV + x0 + tx];
        tile[ty + 8 * j][tx] = v[j];
    }
    #pragma unroll
    for (int j = 0; j < 4; j++) {
        float s = v[j];
        #pragma unroll
        for (int o = 16; o; o >>= 1) s += __shfl_down_sync(0xffffffffu, s, o);
        if (tx == 0) atomicAdd(&g_rs[y0 + ty + 8 * j], s);
    }
    colp[ty * 32 + tx] = v[0] + v[1] + v[2] + v[3];
    __syncthreads();
    if (ty == 0) {
        float s = 0.f;
        #pragma unroll
        for (int w = 0; w < 8; w++) s += colp[w * 32 + tx];
        atomicAdd(&g_csm[x0 + tx], s);
    }
    #pragma unroll
    for (int j = 0; j < 4; j++)
        g_Tth[(size_t)(x0 + ty + 8 * j) * NV + y0 + tx] =
            __float2half_rn(tile[tx][ty + 8 * j] * SC_T);
}

// ---------------------------------------------------------------------------
// Cost kernels with tensor-core gram (bf16). 64x64 tile/block, 8 warps.
// ---------------------------------------------------------------------------
template<bool SELF>
__global__ __launch_bounds__(256) void k_cost_mma(int table,
        const float* __restrict__ aux, const float* __restrict__ mu) {
    const bf16* __restrict__ embA = (SELF && table) ? g_eh2 : g_eh1;
    const bf16* __restrict__ embB = SELF ? embA : g_eh2;
    const float* __restrict__ eA  = (SELF && table) ? g_e2 : g_e1;
    const float* __restrict__ eB  = SELF ? eA : g_e2;
    __half* __restrict__ cost = table ? g_cth : g_csh;
    float* __restrict__ diag = table ? g_db : g_da;
    float* __restrict__ fout = table ? g_f2 : g_f1;
    const float* __restrict__ rv = table ? g_csm : g_rs;

    __shared__ __align__(16) char smA[64 * 272];
    __shared__ __align__(16) char smB[64 * 272];
    __shared__ float red[256];

    int tid = threadIdx.x, wid = tid >> 5, lane = tid & 31;
    int g = lane >> 2, tig = lane & 3;
    int wm = wid >> 2, wn = wid & 3;
    int i0 = blockIdx.y * 64, j0 = blockIdx.x * 64;

    #pragma unroll
    for (int q = 0; q < 4; q++) {
        int idx = tid + 256 * q;
        int row = idx >> 4, c16 = idx & 15;
        *(uint4*)(smA + row * 272 + c16 * 16) =
            *(const uint4*)&embA[(size_t)(i0 + row) * DV + c16 * 8];
        *(uint4*)(smB + row * 272 + c16 * 16) =
            *(const uint4*)&embB[(size_t)(j0 + row) * DV + c16 * 8];
    }
    __syncthreads();

    float acc[2][2][4];
    #pragma unroll
    for (int mi = 0; mi < 2; mi++)
        #pragma unroll
        for (int ni = 0; ni < 2; ni++)
            #pragma unroll
            for (int q = 0; q < 4; q++) acc[mi][ni][q] = 0.f;

    #pragma unroll
    for (int k = 0; k < 8; k++) {
        int kb = k * 32;
        uint32_t afr[2][4], bfr[2][2];
        #pragma unroll
        for (int mi = 0; mi < 2; mi++) {
            const char* ar0 = smA + (wm * 32 + mi * 16 + g) * 272 + kb + tig * 4;
            const char* ar1 = ar0 + 8 * 272;
            afr[mi][0] = *(const uint32_t*)ar0;
            afr[mi][1] = *(const uint32_t*)ar1;
            afr[mi][2] = *(const uint32_t*)(ar0 + 16);
            afr[mi][3] = *(const uint32_t*)(ar1 + 16);
        }
        #pragma unroll
        for (int ni = 0; ni < 2; ni++) {
            const char* br = smB + (wn * 16 + ni * 8 + g) * 272 + kb + tig * 4;
            bfr[ni][0] = *(const uint32_t*)br;
            bfr[ni][1] = *(const uint32_t*)(br + 16);
        }
        #pragma unroll
        for (int mi = 0; mi < 2; mi++)
            #pragma unroll
            for (int ni = 0; ni < 2; ni++)
                mma_bf16(acc[mi][ni], afr[mi], bfr[ni]);
    }

    const float scale = SELF ? 5.0f : 1.0f;
    float sloc = 0.f, qloc = 0.f;
    #pragma unroll
    for (int mi = 0; mi < 2; mi++) {
        int r0 = i0 + wm * 32 + mi * 16 + g;
        int r1 = r0 + 8;
        float ei0 = eA[r0], ei1 = eA[r1];
        float rvi0 = 0.f, rvi1 = 0.f;
        if (SELF) { rvi0 = rv[r0]; rvi1 = rv[r1]; }
        float f0 = 0.f, f1v = 0.f;
        #pragma unroll
        for (int ni = 0; ni < 2; ni++) {
            int col = j0 + wn * 16 + ni * 8 + 2 * tig;
            float ej0 = eB[col], ej1 = eB[col + 1];
            float2 t0 = *(const float2*)&aux[(size_t)r0 * NV + col];
            float2 t1 = *(const float2*)&aux[(size_t)r1 * NV + col];
            float c00 = 1.f - __expf(-scale * (1.f - __fdividef(acc[mi][ni][0], ei0 * ej0 + 1e-5f)));
            float c01 = 1.f - __expf(-scale * (1.f - __fdividef(acc[mi][ni][1], ei0 * ej1 + 1e-5f)));
            float c10 = 1.f - __expf(-scale * (1.f - __fdividef(acc[mi][ni][2], ei1 * ej0 + 1e-5f)));
            float c11 = 1.f - __expf(-scale * (1.f - __fdividef(acc[mi][ni][3], ei1 * ej1 + 1e-5f)));
            if (SELF) {
                float m0 = mu[col], m1 = mu[col + 1];
                float d00 = c00 - t0.x, d01 = c01 - t0.y;
                float d10 = c10 - t1.x, d11 = c11 - t1.y;
                sloc += d00 * d00 * __expf(-t0.x) + d01 * d01 * __expf(-t0.y)
                      + d10 * d10 * __expf(-t1.x) + d11 * d11 * __expf(-t1.y);
                f0  += c00 * c00 * m0 + c01 * c01 * m1;
                f1v += c10 * c10 * m0 + c11 * c11 * m1;
                float v00 = c00 - C0F, v01 = c01 - C0F;
                float v10 = c10 - C0F, v11 = c11 - C0F;
                if (r0 == col)     { diag[r0] = v00; v00 = 0.f; }
                if (r0 == col + 1) { diag[r0] = v01; v01 = 0.f; }
                if (r1 == col)     { diag[r1] = v10; v10 = 0.f; }
                if (r1 == col + 1) { diag[r1] = v11; v11 = 0.f; }
                float rvj0 = rv[col], rvj1 = rv[col + 1];
                qloc += rvi0 * (v00 * rvj0 + v01 * rvj1)
                      + rvi1 * (v10 * rvj0 + v11 * rvj1);
                *(__half2*)&cost[(size_t)r0 * NV + col] = __floats2half2_rn(v00, v01);
                *(__half2*)&cost[(size_t)r1 * NV + col] = __floats2half2_rn(v10, v11);
            } else {
                sloc += c00 * t0.x + c01 * t0.y + c10 * t1.x + c11 * t1.y;
            }
        }
        if (SELF) {
            f0  += __shfl_down_sync(0xffffffffu, f0, 1);
            f0  += __shfl_down_sync(0xffffffffu, f0, 2);
            f1v += __shfl_down_sync(0xffffffffu, f1v, 1);
            f1v += __shfl_down_sync(0xffffffffu, f1v, 2);
            if (tig == 0) {
                atomicAdd(&fout[r0], f0);
                atomicAdd(&fout[r1], f1v);
            }
        }
    }

    red[tid] = sloc;
    __syncthreads();
    #pragma unroll
    for (int s = 128; s; s >>= 1) {
        if (tid < s) red[tid] += red[tid + s];
        __syncthreads();
    }
    if (tid == 0) atomicAdd(&g_acc[SELF ? table : 4], (double)red[0]);

    if (SELF) {
        __syncthreads();
        red[tid] = qloc;
        __syncthreads();
        #pragma unroll
        for (int s = 128; s; s >>= 1) {
            if (tid < s) red[tid] += red[tid + s];
            __syncthreads();
        }
        if (tid == 0) atomicAdd(&g_acc[6 + table], (double)red[0]);
    }
}

// Tiled partial gram for orthogonality.
__global__ __launch_bounds__(256) void k_orth_part() {
    __shared__ float smE[64 * DV];
    int table = blockIdx.y;
    const float* __restrict__ embs = table ? g_embs2 : g_embs1;
    int r0 = blockIdx.x * 64;
    int tid = threadIdx.x;
    for (int idx = tid; idx < 64 * DV; idx += 256)
        smE[idx] = embs[(size_t)(r0 + idx / DV) * DV + (idx % DV)];
    __syncthreads();
    int a = tid & 127;
    int bhalf = tid >> 7;
    float* G = &g_orthG[table * DV * DV];
    #pragma unroll 1
    for (int bp = 0; bp < 4; bp++) {
        float accv[16];
        #pragma unroll
        for (int q = 0; q < 16; q++) accv[q] = 0.f;
        int b0 = bhalf * 64 + bp * 16;
        for (int k = 0; k < 64; k++) {
            float ra = smE[k * DV + a];
            #pragma unroll
            for (int q = 0; q < 16; q++)
                accv[q] += ra * smE[k * DV + b0 + q];
        }
        #pragma unroll
        for (int q = 0; q < 16; q++)
            atomicAdd(&G[a * DV + b0 + q], accv[q]);
    }
}

__global__ void k_orth_fin() {
    __shared__ double red[256][2];
    int t = threadIdx.x;
    double s0 = 0.0, s1 = 0.0;
    for (int i = t; i < 2 * DV * DV; i += 256) {
        int table = i >> 14;
        int rc = i & (DV * DV - 1);
        float v = g_orthG[i] - ((rc >> 7) == (rc & 127) ? 1.f : 0.f);
        double vv = (double)v * v;
        if (table) s1 += vv; else s0 += vv;
    }
    red[t][0] = s0; red[t][1] = s1;
    __syncthreads();
    for (int k = 128; k; k >>= 1) {
        if (t < k) { red[t][0] += red[t + k][0]; red[t][1] += red[t + k][1]; }
        __syncthreads();
    }
    if (t == 0) { atomicAdd(&g_acc[2], red[0][0]); atomicAdd(&g_acc[3], red[0][1]); }
}

// ---------------------------------------------------------------------------
// f16 mma.sync GEMM (f16 accum): CTA 128x128, 512 threads (16 warps, 2x8),
// warp tile 64x16 (4m x 2n frags), BK=32 halves, 4-stage cp.async.
// FUSE=false: X = As@Tt descaled + diag(a)T; store X f16; g_xb[col] partials.
// FUSE=true:  acc[5] += <(X @ Bs), T> descaled.
// ---------------------------------------------------------------------------
constexpr int BKC = 32;
constexpr int NCH = NV / BKC;          // 128
constexpr int SROW = 80;
constexpr int TILEB = 128 * SROW;
constexpr int STAGEB = 2 * TILEB;
constexpr int NSTG = 4;
constexpr uint32_t G_SMEM = NSTG * STAGEB;   // 81920

template<bool FUSE>
__global__ __launch_bounds__(512, 2) void k_mmagemm(const float* __restrict__ T) {
    const __half* __restrict__ A = FUSE ? g_Xh : g_csh;
    const __half* __restrict__ B = FUSE ? g_cth : g_Tth;

    extern __shared__ char sm[];
    const uint32_t smb = smem_u32(sm);
    int tid = threadIdx.x, wid = tid >> 5, lane = tid & 31;
    int m0 = blockIdx.y * 128, n0 = blockIdx.x * 128;
    int wm = wid >> 3, wn = wid & 7;   // 2 x 8 warp grid
    int g = lane >> 2, tig = lane & 3;

    uint32_t hc[8][2];                 // frag = mi*2+ni (mi<4, ni<2)
    #pragma unroll
    for (int f = 0; f < 8; f++) { hc[f][0] = 0u; hc[f][1] = 0u; }

    auto load_chunk = [&](int s, int k0) {
        uint32_t base = smb + (uint32_t)(s * STAGEB);
        #pragma unroll
        for (int q = 0; q < 2; q++) {
            int idx = tid + 512 * q;           // 0..1023
            int isB = idx >> 9;
            int id = idx & 511;
            int row = id >> 2, seg = id & 3;
            const __half* src = isB ? &B[(size_t)(n0 + row) * NV + k0 + seg * 8]
                                    : &A[(size_t)(m0 + row) * NV + k0 + seg * 8];
            uint32_t dst = base + (uint32_t)(isB * TILEB + row * SROW + seg * 16);
            CP16(dst, src);
        }
    };

    #pragma unroll
    for (int s = 0; s < NSTG; s++) { load_chunk(s, s * BKC); CP_COMMIT(); }

    #pragma unroll 1
    for (int c = 0; c < NCH; c++) {
        int s = c & (NSTG - 1);
        CP_WAIT3();
        __syncthreads();
        const char* As = sm + s * STAGEB;
        const char* Bs = As + TILEB;
        #pragma unroll
        for (int ks = 0; ks < 2; ks++) {
            int kb = ks * 32;
            uint32_t afr[4][4], bfr[2][2];
            #pragma unroll
            for (int mi = 0; mi < 4; mi++) {
                int rb = wm * 64 + mi * 16;
                const char* ar0 = As + (rb + g) * SROW + kb + tig * 4;
                const char* ar1 = As + (rb + g + 8) * SROW + kb + tig * 4;
                afr[mi][0] = *(const uint32_t*)ar0;
                afr[mi][1] = *(const uint32_t*)ar1;
                afr[mi][2] = *(const uint32_t*)(ar0 + 16);
                afr[mi][3] = *(const uint32_t*)(ar1 + 16);
            }
            #pragma unroll
            for (int ni = 0; ni < 2; ni++) {
                int nb = wn * 16 + ni * 8;
                const char* br = Bs + (nb + g) * SROW + kb + tig * 4;
                bfr[ni][0] = *(const uint32_t*)br;
                bfr[ni][1] = *(const uint32_t*)(br + 16);
            }
            #pragma unroll
            for (int mi = 0; mi < 4; mi++)
                #pragma unroll
                for (int ni = 0; ni < 2; ni++)
                    mma_f16h(hc[mi * 2 + ni], afr[mi], bfr[ni]);
        }
        __syncthreads();
        if (c + NSTG < NCH) load_chunk(s, (c + NSTG) * BKC);
        CP_COMMIT();
    }

    float acc[4][2][4];
    #pragma unroll
    for (int mi = 0; mi < 4; mi++)
        #pragma unroll
        for (int ni = 0; ni < 2; ni++) {
            float2 lo = __half22float2(*(__half2*)&hc[mi * 2 + ni][0]);
            float2 hi = __half22float2(*(__half2*)&hc[mi * 2 + ni][1]);
            acc[mi][ni][0] = lo.x; acc[mi][ni][1] = lo.y;
            acc[mi][ni][2] = hi.x; acc[mi][ni][3] = hi.y;
        }

    if (!FUSE) {
        float cpart[4];
        #pragma unroll
        for (int q = 0; q < 4; q++) cpart[q] = 0.f;
        #pragma unroll
        for (int mi = 0; mi < 4; mi++) {
            int r0 = m0 + wm * 64 + mi * 16 + g;
            int r1 = r0 + 8;
            float da0 = g_da[r0], da1 = g_da[r1];
            #pragma unroll
            for (int ni = 0; ni < 2; ni++) {
                int col = n0 + wn * 16 + ni * 8 + 2 * tig;
                float2 t0 = *(const float2*)&T[(size_t)r0 * NV + col];
                float2 t1 = *(const float2*)&T[(size_t)r1 * NV + col];
                float x00 = acc[mi][ni][0] * INV_G1 + da0 * t0.x;
                float x01 = acc[mi][ni][1] * INV_G1 + da0 * t0.y;
                float x10 = acc[mi][ni][2] * INV_G1 + da1 * t1.x;
                float x11 = acc[mi][ni][3] * INV_G1 + da1 * t1.y;
                cpart[ni * 2 + 0] += t0.x * x00 + t1.x * x10;
                cpart[ni * 2 + 1] += t0.y * x01 + t1.y * x11;
                *(__half2*)&g_Xh[(size_t)r0 * NV + col] =
                    __floats2half2_rn(x00 * SC_X, x01 * SC_X);
                *(__half2*)&g_Xh[(size_t)r1 * NV + col] =
                    __floats2half2_rn(x10 * SC_X, x11 * SC_X);
            }
        }
        __syncthreads();
        float* colacc = (float*)sm;
        if (tid < 128) colacc[tid] = 0.f;
        __syncthreads();
        #pragma unroll
        for (int ni = 0; ni < 2; ni++) {
            int cl = wn * 16 + ni * 8 + 2 * tig;
            atomicAdd(&colacc[cl], cpart[ni * 2 + 0]);
            atomicAdd(&colacc[cl + 1], cpart[ni * 2 + 1]);
        }
        __syncthreads();
        if (tid < 128) atomicAdd(&g_xb[n0 + tid], colacc[tid]);
    } else {
        float loc = 0.f;
        #pragma unroll
        for (int mi = 0; mi < 4; mi++) {
            int r0 = m0 + wm * 64 + mi * 16 + g;
            int r1 = r0 + 8;
            #pragma unroll
            for (int ni = 0; ni < 2; ni++) {
                int col = n0 + wn * 16 + ni * 8 + 2 * tig;
                float2 t0 = *(const float2*)&T[(size_t)r0 * NV + col];
                float2 t1 = *(const float2*)&T[(size_t)r1 * NV + col];
                loc += acc[mi][ni][0] * t0.x + acc[mi][ni][1] * t0.y
                     + acc[mi][ni][2] * t1.x + acc[mi][ni][3] * t1.y;
            }
        }
        __syncthreads();
        float* red = (float*)sm;
        red[tid] = loc;
        __syncthreads();
        #pragma unroll
        for (int s = 256; s; s >>= 1) {
            if (tid < s) red[tid] += red[tid + s];
            __syncthreads();
        }
        if (tid == 0) atomicAdd(&g_acc[5], (double)red[0] * INV_G2);
    }
}

__global__ void k_finalize(float* __restrict__ out) {
    __shared__ double s0[256], s1[256], s2[256], s3[256];
    int t = threadIdx.x;
    double a = 0.0, b = 0.0, c = 0.0, d = 0.0;
    for (int i = t; i < NV; i += 256) {
        double rs = g_rs[i], cs = g_csm[i];
        a += (double)g_f1[i] * rs + (double)g_f2[i] * cs;
        b += rs;
        c += (double)g_da[i] * rs * rs + (double)g_db[i] * cs * cs;
        d += (double)g_xb[i] * (double)g_db[i];
    }
    s0[t] = a; s1[t] = b; s2[t] = c; s3[t] = d;
    __syncthreads();
    for (int k = 128; k; k >>= 1) {
        if (t < k) { s0[t] += s0[t+k]; s1[t] += s1[t+k]; s2[t] += s2[t+k]; s3[t] += s3[t+k]; }
        __syncthreads();
    }
    if (t == 0) {
        const double c0 = (double)C0F;
        double S = s1[0];
        double inner = c0 * c0 * S * S
                     + c0 * (g_acc[6] + g_acc[7] + s2[0])
                     + g_acc[5] + s3[0];
        out[0] = (float)(s0[0] - 2.0 * inner);
        out[1] = (float)g_acc[4];
        out[2] = (float)(g_acc[0] + g_acc[1] + g_acc[2] + g_acc[3]);
    }
}

// ---------------------------------------------------------------------------
extern "C" void kernel_launch(void* const* d_in, const int* in_sizes, int n_in,
                              void* d_out, int out_size) {
    const int*   index1 = (const int*)d_in[0];
    const int*   index2 = (const int*)d_in[1];
    const float* trans  = (const float*)d_in[2];
    const float* mu_s   = (const float*)d_in[3];
    const float* mu_t   = (const float*)d_in[4];
    const float* cost1  = (const float*)d_in[5];
    const float* cost2  = (const float*)d_in[6];
    const float* emb1_w = (const float*)d_in[7];
    const float* emb2_w = (const float*)d_in[8];
    float* out = (float*)d_out;

    static cudaStream_t s_side = nullptr;
    static cudaEvent_t e_init = nullptr, e_gather = nullptr, e_tpass = nullptr,
                       e_cost1 = nullptr, e_side = nullptr;
    if (!s_side) {
        cudaStreamCreateWithFlags(&s_side, cudaStreamNonBlocking);
        cudaEventCreateWithFlags(&e_init, cudaEventDisableTiming);
        cudaEventCreateWithFlags(&e_gather, cudaEventDisableTiming);
        cudaEventCreateWithFlags(&e_tpass, cudaEventDisableTiming);
        cudaEventCreateWithFlags(&e_cost1, cudaEventDisableTiming);
        cudaEventCreateWithFlags(&e_side, cudaEventDisableTiming);
        cudaFuncSetAttribute(k_mmagemm<false>, cudaFuncAttributeMaxDynamicSharedMemorySize, G_SMEM);
        cudaFuncSetAttribute(k_mmagemm<true>,  cudaFuncAttributeMaxDynamicSharedMemorySize, G_SMEM);
    }

    dim3 g64(NV / 64, NV / 64);
    dim3 gtc(NV / 128, NV / 128);

    // main: init -> gather -> (wait tpass) -> cost0 -> GEMM1 -> GEMM2 -> finalize
    // side: (wait init) tpass -> (wait gather) cost1 -> d_w -> orth
    k_init<<<128, 256>>>();
    cudaEventRecord(e_init, 0);

    cudaStreamWaitEvent(s_side, e_init, 0);
    k_tpass<<<dim3(NV / 32, NV / 32), dim3(32, 8), 0, s_side>>>(trans);
    cudaEventRecord(e_tpass, s_side);

    k_gather<<<2 * NV, DV>>>(index1, index2, emb1_w, emb2_w);
    cudaEventRecord(e_gather, 0);

    cudaStreamWaitEvent(s_side, e_gather, 0);
    k_cost_mma<true><<<g64, 256, 0, s_side>>>(1, cost2, mu_t);     // Dt + qform
    cudaEventRecord(e_cost1, s_side);
    k_cost_mma<false><<<g64, 256, 0, s_side>>>(0, trans, nullptr); // d_w
    k_orth_part<<<dim3(64, 2), 256, 0, s_side>>>();
    k_orth_fin<<<1, 256, 0, s_side>>>();
    cudaEventRecord(e_side, s_side);

    cudaStreamWaitEvent(0, e_tpass, 0);
    k_cost_mma<true><<<g64, 256>>>(0, cost1, mu_s);                // Ds + qform
    k_mmagemm<false><<<gtc, 512, G_SMEM>>>(trans);                 // X = Ds@T
    cudaStreamWaitEvent(0, e_cost1, 0);
    k_mmagemm<true><<<gtc, 512, G_SMEM>>>(trans);                  // <T, X@Dt>
    cudaStreamWaitEvent(0, e_side, 0);
    k_finalize<<<1, 256>>>(out);
}

// round 16
// speedup vs baseline: 1.2142x; 1.2142x over previous
#include <cuda_runtime.h>
#include <cuda_bf16.h>
#include <cuda_fp16.h>
#include <cstdint>

// ---------------------------------------------------------------------------
// GromovWassersteinEmbedding — GB300 sm_103a (target sm_103 => mma.sync path)
//
//   d_gw = f1·rs + f2·csm - 2*<T, Cs T Ct>
//   Cs = c0·J + diag(a) + As,  Ct = c0·J + diag(b) + Bs
//   <T,CsTCt> = c0²S² + c0·(rsᵀDs rs + csmᵀDt csm) + <T, Ds T Dt>
//     rank-one forms EXACT fp32 in cost kernels; residual via f16 mma.sync
//     GEMMs (f16 accum) at the measured legacy-HMMA floor (R14 config:
//     256 threads, 8 warps, 64x32 warp tiles, BK=32, 4-stage cp.async).
//   X = Ds T = (As@T) descaled + diag(a)·T (fp32 epilogue), stored f16.
//   <T, Ds T Dt> = <T, X@Bs> + Σ_j xb[j]·db[j].
//   Scales: Ds,Dt ×1, T ×2^23, X ×2^27.
//   Streams: side hides tpass (∥ gather) then cost1/d_w/orth under GEMM1.
// ---------------------------------------------------------------------------

using bf16 = __nv_bfloat16;

constexpr int NV = 4096;
constexpr int DV = 128;
constexpr float C0F = 0.99326205f;
constexpr float SC_T = 8388608.f;          // 2^23
constexpr float SC_X = 134217728.f;        // 2^27
constexpr float INV_G1 = 1.f / SC_T;
constexpr double INV_G2 = 1.0 / (double)SC_X;

__device__ float   g_embs1[NV * DV];
__device__ float   g_embs2[NV * DV];
__device__ bf16    g_eh1[NV * DV];
__device__ bf16    g_eh2[NV * DV];
__device__ float   g_e1[NV];
__device__ float   g_e2[NV];
__device__ __half  g_csh[(size_t)NV * NV];
__device__ __half  g_cth[(size_t)NV * NV];
__device__ __half  g_Tth[(size_t)NV * NV];
__device__ __half  g_Xh [(size_t)NV * NV];
__device__ float   g_da[NV];
__device__ float   g_db[NV];
__device__ float   g_f1[NV];
__device__ float   g_f2[NV];
__device__ float   g_rs[NV];
__device__ float   g_csm[NV];
__device__ float   g_xb[NV];
__device__ float   g_orthG[2 * DV * DV];
__device__ double  g_acc[16];

// ------------------------------- helpers -----------------------------------
__device__ __forceinline__ uint32_t smem_u32(const void* p) {
    uint32_t a;
    asm("{ .reg .u64 t; cvta.to.shared.u64 t, %1; cvt.u32.u64 %0, t; }" : "=r"(a) : "l"(p));
    return a;
}
#define CP16(dst, src) \
    asm volatile("cp.async.cg.shared.global [%0], [%1], 16;" :: "r"(dst), "l"(src))
#define CP_COMMIT() asm volatile("cp.async.commit_group;" ::: "memory")
#define CP_WAIT3()  asm volatile("cp.async.wait_group 3;" ::: "memory")

__device__ __forceinline__ void mma_bf16(float c[4], const uint32_t a[4], const uint32_t b[2]) {
    asm volatile("mma.sync.aligned.m16n8k16.row.col.f32.bf16.bf16.f32 "
                 "{%0,%1,%2,%3}, {%4,%5,%6,%7}, {%8,%9}, {%0,%1,%2,%3};"
                 : "+f"(c[0]), "+f"(c[1]), "+f"(c[2]), "+f"(c[3])
                 : "r"(a[0]), "r"(a[1]), "r"(a[2]), "r"(a[3]),
                   "r"(b[0]), "r"(b[1]));
}
__device__ __forceinline__ void mma_f16h(uint32_t c[2], const uint32_t a[4], const uint32_t b[2]) {
    asm volatile("mma.sync.aligned.m16n8k16.row.col.f16.f16.f16.f16 "
                 "{%0,%1}, {%2,%3,%4,%5}, {%6,%7}, {%0,%1};"
                 : "+r"(c[0]), "+r"(c[1])
                 : "r"(a[0]), "r"(a[1]), "r"(a[2]), "r"(a[3]),
                   "r"(b[0]), "r"(b[1]));
}

// ---------------------------------------------------------------------------
__global__ void k_init() {
    int i = blockIdx.x * blockDim.x + threadIdx.x;
    if (i < 2 * DV * DV) g_orthG[i] = 0.f;
    if (i < NV) { g_f1[i] = 0.f; g_f2[i] = 0.f; g_csm[i] = 0.f; g_rs[i] = 0.f; g_xb[i] = 0.f; }
    if (i < 16) g_acc[i] = 0.0;
}

__global__ void k_gather(const int* __restrict__ idx1, const int* __restrict__ idx2,
                         const float* __restrict__ w1, const float* __restrict__ w2) {
    int b = blockIdx.x;
    int table = b >> 12;
    int row = b & (NV - 1);
    const int* __restrict__ idx = table ? idx2 : idx1;
    const float* __restrict__ w = table ? w2 : w1;
    float* embs = table ? g_embs2 : g_embs1;
    bf16* embh = table ? g_eh2 : g_eh1;
    float* e = table ? g_e2 : g_e1;
    int t = threadIdx.x;
    float v = w[(size_t)idx[row] * DV + t];
    embs[row * DV + t] = v;
    embh[row * DV + t] = __float2bfloat16(v);
    float s = v * v;
    #pragma unroll
    for (int o = 16; o; o >>= 1) s += __shfl_down_sync(0xffffffffu, s, o);
    __shared__ float ws[4];
    if ((t & 31) == 0) ws[t >> 5] = s;
    __syncthreads();
    if (t == 0) e[row] = sqrtf(ws[0] + ws[1] + ws[2] + ws[3]);
}

// Fused T pass: rowsum + colsum + transposed f16 quantization.
__global__ void k_tpass(const float* __restrict__ T) {
    __shared__ float tile[32][33];
    __shared__ float colp[256];
    int x0 = blockIdx.x * 32, y0 = blockIdx.y * 32;
    int tx = threadIdx.x, ty = threadIdx.y;
    float v[4];
    #pragma unroll
    for (int j = 0; j < 4; j++) {
        v[j] = T[(size_t)(y0 + ty + 8 * j) * NV + x0 + tx];
        tile[ty + 8 * j][tx] = v[j];
    }
    #pragma unroll
    for (int j = 0; j < 4; j++) {
        float s = v[j];
        #pragma unroll
        for (int o = 16; o; o >>= 1) s += __shfl_down_sync(0xffffffffu, s, o);
        if (tx == 0) atomicAdd(&g_rs[y0 + ty + 8 * j], s);
    }
    colp[ty * 32 + tx] = v[0] + v[1] + v[2] + v[3];
    __syncthreads();
    if (ty == 0) {
        float s = 0.f;
        #pragma unroll
        for (int w = 0; w < 8; w++) s += colp[w * 32 + tx];
        atomicAdd(&g_csm[x0 + tx], s);
    }
    #pragma unroll
    for (int j = 0; j < 4; j++)
        g_Tth[(size_t)(x0 + ty + 8 * j) * NV + y0 + tx] =
            __float2half_rn(tile[tx][ty + 8 * j] * SC_T);
}

// ---------------------------------------------------------------------------
// Cost kernels with tensor-core gram (bf16). 64x64 tile/block, 8 warps.
// ---------------------------------------------------------------------------
template<bool SELF>
__global__ __launch_bounds__(256) void k_cost_mma(int table,
        const float* __restrict__ aux, const float* __restrict__ mu) {
    const bf16* __restrict__ embA = (SELF && table) ? g_eh2 : g_eh1;
    const bf16* __restrict__ embB = SELF ? embA : g_eh2;
    const float* __restrict__ eA  = (SELF && table) ? g_e2 : g_e1;
    const float* __restrict__ eB  = SELF ? eA : g_e2;
    __half* __restrict__ cost = table ? g_cth : g_csh;
    float* __restrict__ diag = table ? g_db : g_da;
    float* __restrict__ fout = table ? g_f2 : g_f1;
    const float* __restrict__ rv = table ? g_csm : g_rs;

    __shared__ __align__(16) char smA[64 * 272];
    __shared__ __align__(16) char smB[64 * 272];
    __shared__ float red[256];

    int tid = threadIdx.x, wid = tid >> 5, lane = tid & 31;
    int g = lane >> 2, tig = lane & 3;
    int wm = wid >> 2, wn = wid & 3;
    int i0 = blockIdx.y * 64, j0 = blockIdx.x * 64;

    #pragma unroll
    for (int q = 0; q < 4; q++) {
        int idx = tid + 256 * q;
        int row = idx >> 4, c16 = idx & 15;
        *(uint4*)(smA + row * 272 + c16 * 16) =
            *(const uint4*)&embA[(size_t)(i0 + row) * DV + c16 * 8];
        *(uint4*)(smB + row * 272 + c16 * 16) =
            *(const uint4*)&embB[(size_t)(j0 + row) * DV + c16 * 8];
    }
    __syncthreads();

    float acc[2][2][4];
    #pragma unroll
    for (int mi = 0; mi < 2; mi++)
        #pragma unroll
        for (int ni = 0; ni < 2; ni++)
            #pragma unroll
            for (int q = 0; q < 4; q++) acc[mi][ni][q] = 0.f;

    #pragma unroll
    for (int k = 0; k < 8; k++) {
        int kb = k * 32;
        uint32_t afr[2][4], bfr[2][2];
        #pragma unroll
        for (int mi = 0; mi < 2; mi++) {
            const char* ar0 = smA + (wm * 32 + mi * 16 + g) * 272 + kb + tig * 4;
            const char* ar1 = ar0 + 8 * 272;
            afr[mi][0] = *(const uint32_t*)ar0;
            afr[mi][1] = *(const uint32_t*)ar1;
            afr[mi][2] = *(const uint32_t*)(ar0 + 16);
            afr[mi][3] = *(const uint32_t*)(ar1 + 16);
        }
        #pragma unroll
        for (int ni = 0; ni < 2; ni++) {
            const char* br = smB + (wn * 16 + ni * 8 + g) * 272 + kb + tig * 4;
            bfr[ni][0] = *(const uint32_t*)br;
            bfr[ni][1] = *(const uint32_t*)(br + 16);
        }
        #pragma unroll
        for (int mi = 0; mi < 2; mi++)
            #pragma unroll
            for (int ni = 0; ni < 2; ni++)
                mma_bf16(acc[mi][ni], afr[mi], bfr[ni]);
    }

    const float scale = SELF ? 5.0f : 1.0f;
    float sloc = 0.f, qloc = 0.f;
    #pragma unroll
    for (int mi = 0; mi < 2; mi++) {
        int r0 = i0 + wm * 32 + mi * 16 + g;
        int r1 = r0 + 8;
        float ei0 = eA[r0], ei1 = eA[r1];
        float rvi0 = 0.f, rvi1 = 0.f;
        if (SELF) { rvi0 = rv[r0]; rvi1 = rv[r1]; }
        float f0 = 0.f, f1v = 0.f;
        #pragma unroll
        for (int ni = 0; ni < 2; ni++) {
            int col = j0 + wn * 16 + ni * 8 + 2 * tig;
            float ej0 = eB[col], ej1 = eB[col + 1];
            float2 t0 = *(const float2*)&aux[(size_t)r0 * NV + col];
            float2 t1 = *(const float2*)&aux[(size_t)r1 * NV + col];
            float c00 = 1.f - __expf(-scale * (1.f - __fdividef(acc[mi][ni][0], ei0 * ej0 + 1e-5f)));
            float c01 = 1.f - __expf(-scale * (1.f - __fdividef(acc[mi][ni][1], ei0 * ej1 + 1e-5f)));
            float c10 = 1.f - __expf(-scale * (1.f - __fdividef(acc[mi][ni][2], ei1 * ej0 + 1e-5f)));
            float c11 = 1.f - __expf(-scale * (1.f - __fdividef(acc[mi][ni][3], ei1 * ej1 + 1e-5f)));
            if (SELF) {
                float m0 = mu[col], m1 = mu[col + 1];
                float d00 = c00 - t0.x, d01 = c01 - t0.y;
                float d10 = c10 - t1.x, d11 = c11 - t1.y;
                sloc += d00 * d00 * __expf(-t0.x) + d01 * d01 * __expf(-t0.y)
                      + d10 * d10 * __expf(-t1.x) + d11 * d11 * __expf(-t1.y);
                f0  += c00 * c00 * m0 + c01 * c01 * m1;
                f1v += c10 * c10 * m0 + c11 * c11 * m1;
                float v00 = c00 - C0F, v01 = c01 - C0F;
                float v10 = c10 - C0F, v11 = c11 - C0F;
                if (r0 == col)     { diag[r0] = v00; v00 = 0.f; }
                if (r0 == col + 1) { diag[r0] = v01; v01 = 0.f; }
                if (r1 == col)     { diag[r1] = v10; v10 = 0.f; }
                if (r1 == col + 1) { diag[r1] = v11; v11 = 0.f; }
                float rvj0 = rv[col], rvj1 = rv[col + 1];
                qloc += rvi0 * (v00 * rvj0 + v01 * rvj1)
                      + rvi1 * (v10 * rvj0 + v11 * rvj1);
                *(__half2*)&cost[(size_t)r0 * NV + col] = __floats2half2_rn(v00, v01);
                *(__half2*)&cost[(size_t)r1 * NV + col] = __floats2half2_rn(v10, v11);
            } else {
                sloc += c00 * t0.x + c01 * t0.y + c10 * t1.x + c11 * t1.y;
            }
        }
        if (SELF) {
            f0  += __shfl_down_sync(0xffffffffu, f0, 1);
            f0  += __shfl_down_sync(0xffffffffu, f0, 2);
            f1v += __shfl_down_sync(0xffffffffu, f1v, 1);
            f1v += __shfl_down_sync(0xffffffffu, f1v, 2);
            if (tig == 0) {
                atomicAdd(&fout[r0], f0);
                atomicAdd(&fout[r1], f1v);
            }
        }
    }

    red[tid] = sloc;
    __syncthreads();
    #pragma unroll
    for (int s = 128; s; s >>= 1) {
        if (tid < s) red[tid] += red[tid + s];
        __syncthreads();
    }
    if (tid == 0) atomicAdd(&g_acc[SELF ? table : 4], (double)red[0]);

    if (SELF) {
        __syncthreads();
        red[tid] = qloc;
        __syncthreads();
        #pragma unroll
        for (int s = 128; s; s >>= 1) {
            if (tid < s) red[tid] += red[tid + s];
            __syncthreads();
        }
        if (tid == 0) atomicAdd(&g_acc[6 + table], (double)red[0]);
    }
}

// Tiled partial gram for orthogonality.
__global__ __launch_bounds__(256) void k_orth_part() {
    __shared__ float smE[64 * DV];
    int table = blockIdx.y;
    const float* __restrict__ embs = table ? g_embs2 : g_embs1;
    int r0 = blockIdx.x * 64;
    int tid = threadIdx.x;
    for (int idx = tid; idx < 64 * DV; idx += 256)
        smE[idx] = embs[(size_t)(r0 + idx / DV) * DV + (idx % DV)];
    __syncthreads();
    int a = tid & 127;
    int bhalf = tid >> 7;
    float* G = &g_orthG[table * DV * DV];
    #pragma unroll 1
    for (int bp = 0; bp < 4; bp++) {
        float accv[16];
        #pragma unroll
        for (int q = 0; q < 16; q++) accv[q] = 0.f;
        int b0 = bhalf * 64 + bp * 16;
        for (int k = 0; k < 64; k++) {
            float ra = smE[k * DV + a];
            #pragma unroll
            for (int q = 0; q < 16; q++)
                accv[q] += ra * smE[k * DV + b0 + q];
        }
        #pragma unroll
        for (int q = 0; q < 16; q++)
            atomicAdd(&G[a * DV + b0 + q], accv[q]);
    }
}

__global__ void k_orth_fin() {
    __shared__ double red[256][2];
    int t = threadIdx.x;
    double s0 = 0.0, s1 = 0.0;
    for (int i = t; i < 2 * DV * DV; i += 256) {
        int table = i >> 14;
        int rc = i & (DV * DV - 1);
        float v = g_orthG[i] - ((rc >> 7) == (rc & 127) ? 1.f : 0.f);
        double vv = (double)v * v;
        if (table) s1 += vv; else s0 += vv;
    }
    red[t][0] = s0; red[t][1] = s1;
    __syncthreads();
    for (int k = 128; k; k >>= 1) {
        if (t < k) { red[t][0] += red[t + k][0]; red[t][1] += red[t + k][1]; }
        __syncthreads();
    }
    if (t == 0) { atomicAdd(&g_acc[2], red[0][0]); atomicAdd(&g_acc[3], red[0][1]); }
}

// ---------------------------------------------------------------------------
// f16 mma.sync GEMM (f16 accum): CTA 128x128, 256 threads (8 warps, 2x4),
// warp tile 64x32, BK=32 halves, 4-stage cp.async — measured-best config.
// FUSE=false: X = As@Tt descaled + diag(a)T; store X f16; g_xb[col] partials.
// FUSE=true:  acc[5] += <(X @ Bs), T> descaled.
// ---------------------------------------------------------------------------
constexpr int BKC = 32;
constexpr int NCH = NV / BKC;          // 128
constexpr int SROW = 80;
constexpr int TILEB = 128 * SROW;
constexpr int STAGEB = 2 * TILEB;
constexpr int NSTG = 4;
constexpr uint32_t G_SMEM = NSTG * STAGEB;   // 81920

template<bool FUSE>
__global__ __launch_bounds__(256, 2) void k_mmagemm(const float* __restrict__ T) {
    const __half* __restrict__ A = FUSE ? g_Xh : g_csh;
    const __half* __restrict__ B = FUSE ? g_cth : g_Tth;

    extern __shared__ char sm[];
    const uint32_t smb = smem_u32(sm);
    int tid = threadIdx.x, wid = tid >> 5, lane = tid & 31;
    int m0 = blockIdx.y * 128, n0 = blockIdx.x * 128;
    int wm = wid >> 2, wn = wid & 3;
    int g = lane >> 2, tig = lane & 3;

    uint32_t hc[16][2];
    #pragma unroll
    for (int f = 0; f < 16; f++) { hc[f][0] = 0u; hc[f][1] = 0u; }

    auto load_chunk = [&](int s, int k0) {
        uint32_t base = smb + (uint32_t)(s * STAGEB);
        #pragma unroll
        for (int q = 0; q < 4; q++) {
            int idx = tid + 256 * q;
            int isB = idx >> 9;
            int id = idx & 511;
            int row = id >> 2, seg = id & 3;
            const __half* src = isB ? &B[(size_t)(n0 + row) * NV + k0 + seg * 8]
                                    : &A[(size_t)(m0 + row) * NV + k0 + seg * 8];
            uint32_t dst = base + (uint32_t)(isB * TILEB + row * SROW + seg * 16);
            CP16(dst, src);
        }
    };

    #pragma unroll
    for (int s = 0; s < NSTG; s++) { load_chunk(s, s * BKC); CP_COMMIT(); }

    #pragma unroll 1
    for (int c = 0; c < NCH; c++) {
        int s = c & (NSTG - 1);
        CP_WAIT3();
        __syncthreads();
        const char* As = sm + s * STAGEB;
        const char* Bs = As + TILEB;
        #pragma unroll
        for (int ks = 0; ks < 2; ks++) {
            int kb = ks * 32;
            uint32_t afr[4][4], bfr[4][2];
            #pragma unroll
            for (int mi = 0; mi < 4; mi++) {
                int rb = wm * 64 + mi * 16;
                const char* ar0 = As + (rb + g) * SROW + kb + tig * 4;
                const char* ar1 = As + (rb + g + 8) * SROW + kb + tig * 4;
                afr[mi][0] = *(const uint32_t*)ar0;
                afr[mi][1] = *(const uint32_t*)ar1;
                afr[mi][2] = *(const uint32_t*)(ar0 + 16);
                afr[mi][3] = *(const uint32_t*)(ar1 + 16);
            }
            #pragma unroll
            for (int ni = 0; ni < 4; ni++) {
                int nb = wn * 32 + ni * 8;
                const char* br = Bs + (nb + g) * SROW + kb + tig * 4;
                bfr[ni][0] = *(const uint32_t*)br;
                bfr[ni][1] = *(const uint32_t*)(br + 16);
            }
            #pragma unroll
            for (int mi = 0; mi < 4; mi++)
                #pragma unroll
                for (int ni = 0; ni < 4; ni++)
                    mma_f16h(hc[mi * 4 + ni], afr[mi], bfr[ni]);
        }
        __syncthreads();
        if (c + NSTG < NCH) load_chunk(s, (c + NSTG) * BKC);
        CP_COMMIT();
    }

    float acc[4][4][4];
    #pragma unroll
    for (int mi = 0; mi < 4; mi++)
        #pragma unroll
        for (int ni = 0; ni < 4; ni++) {
            float2 lo = __half22float2(*(__half2*)&hc[mi * 4 + ni][0]);
            float2 hi = __half22float2(*(__half2*)&hc[mi * 4 + ni][1]);
            acc[mi][ni][0] = lo.x; acc[mi][ni][1] = lo.y;
            acc[mi][ni][2] = hi.x; acc[mi][ni][3] = hi.y;
        }

    if (!FUSE) {
        float cpart[8];
        #pragma unroll
        for (int q = 0; q < 8; q++) cpart[q] = 0.f;
        #pragma unroll
        for (int mi = 0; mi < 4; mi++) {
            int r0 = m0 + wm * 64 + mi * 16 + g;
            int r1 = r0 + 8;
            float da0 = g_da[r0], da1 = g_da[r1];
            #pragma unroll
            for (int ni = 0; ni < 4; ni++) {
                int col = n0 + wn * 32 + ni * 8 + 2 * tig;
                float2 t0 = *(const float2*)&T[(size_t)r0 * NV + col];
                float2 t1 = *(const float2*)&T[(size_t)r1 * NV + col];
                float x00 = acc[mi][ni][0] * INV_G1 + da0 * t0.x;
                float x01 = acc[mi][ni][1] * INV_G1 + da0 * t0.y;
                float x10 = acc[mi][ni][2] * INV_G1 + da1 * t1.x;
                float x11 = acc[mi][ni][3] * INV_G1 + da1 * t1.y;
                cpart[ni * 2 + 0] += t0.x * x00 + t1.x * x10;
                cpart[ni * 2 + 1] += t0.y * x01 + t1.y * x11;
                *(__half2*)&g_Xh[(size_t)r0 * NV + col] =
                    __floats2half2_rn(x00 * SC_X, x01 * SC_X);
                *(__half2*)&g_Xh[(size_t)r1 * NV + col] =
                    __floats2half2_rn(x10 * SC_X, x11 * SC_X);
            }
        }
        __syncthreads();
        float* colacc = (float*)sm;
        if (tid < 128) colacc[tid] = 0.f;
        __syncthreads();
        #pragma unroll
        for (int ni = 0; ni < 4; ni++) {
            int cl = wn * 32 + ni * 8 + 2 * tig;
            atomicAdd(&colacc[cl], cpart[ni * 2 + 0]);
            atomicAdd(&colacc[cl + 1], cpart[ni * 2 + 1]);
        }
        __syncthreads();
        if (tid < 128) atomicAdd(&g_xb[n0 + tid], colacc[tid]);
    } else {
        float loc = 0.f;
        #pragma unroll
        for (int mi = 0; mi < 4; mi++) {
            int r0 = m0 + wm * 64 + mi * 16 + g;
            int r1 = r0 + 8;
            #pragma unroll
            for (int ni = 0; ni < 4; ni++) {
                int col = n0 + wn * 32 + ni * 8 + 2 * tig;
                float2 t0 = *(const float2*)&T[(size_t)r0 * NV + col];
                float2 t1 = *(const float2*)&T[(size_t)r1 * NV + col];
                loc += acc[mi][ni][0] * t0.x + acc[mi][ni][1] * t0.y
                     + acc[mi][ni][2] * t1.x + acc[mi][ni][3] * t1.y;
            }
        }
        __syncthreads();
        float* red = (float*)sm;
        red[tid] = loc;
        __syncthreads();
        #pragma unroll
        for (int s = 128; s; s >>= 1) {
            if (tid < s) red[tid] += red[tid + s];
            __syncthreads();
        }
        if (tid == 0) atomicAdd(&g_acc[5], (double)red[0] * INV_G2);
    }
}

__global__ void k_finalize(float* __restrict__ out) {
    __shared__ double s0[256], s1[256], s2[256], s3[256];
    int t = threadIdx.x;
    double a = 0.0, b = 0.0, c = 0.0, d = 0.0;
    for (int i = t; i < NV; i += 256) {
        double rs = g_rs[i], cs = g_csm[i];
        a += (double)g_f1[i] * rs + (double)g_f2[i] * cs;
        b += rs;
        c += (double)g_da[i] * rs * rs + (double)g_db[i] * cs * cs;
        d += (double)g_xb[i] * (double)g_db[i];
    }
    s0[t] = a; s1[t] = b; s2[t] = c; s3[t] = d;
    __syncthreads();
    for (int k = 128; k; k >>= 1) {
        if (t < k) { s0[t] += s0[t+k]; s1[t] += s1[t+k]; s2[t] += s2[t+k]; s3[t] += s3[t+k]; }
        __syncthreads();
    }
    if (t == 0) {
        const double c0 = (double)C0F;
        double S = s1[0];
        double inner = c0 * c0 * S * S
                     + c0 * (g_acc[6] + g_acc[7] + s2[0])
                     + g_acc[5] + s3[0];
        out[0] = (float)(s0[0] - 2.0 * inner);
        out[1] = (float)g_acc[4];
        out[2] = (float)(g_acc[0] + g_acc[1] + g_acc[2] + g_acc[3]);
    }
}

// ---------------------------------------------------------------------------
extern "C" void kernel_launch(void* const* d_in, const int* in_sizes, int n_in,
                              void* d_out, int out_size) {
    const int*   index1 = (const int*)d_in[0];
    const int*   index2 = (const int*)d_in[1];
    const float* trans  = (const float*)d_in[2];
    const float* mu_s   = (const float*)d_in[3];
    const float* mu_t   = (const float*)d_in[4];
    const float* cost1  = (const float*)d_in[5];
    const float* cost2  = (const float*)d_in[6];
    const float* emb1_w = (const float*)d_in[7];
    const float* emb2_w = (const float*)d_in[8];
    float* out = (float*)d_out;

    static cudaStream_t s_side = nullptr;
    static cudaEvent_t e_init = nullptr, e_gather = nullptr, e_tpass = nullptr,
                       e_cost1 = nullptr, e_side = nullptr;
    if (!s_side) {
        cudaStreamCreateWithFlags(&s_side, cudaStreamNonBlocking);
        cudaEventCreateWithFlags(&e_init, cudaEventDisableTiming);
        cudaEventCreateWithFlags(&e_gather, cudaEventDisableTiming);
        cudaEventCreateWithFlags(&e_tpass, cudaEventDisableTiming);
        cudaEventCreateWithFlags(&e_cost1, cudaEventDisableTiming);
        cudaEventCreateWithFlags(&e_side, cudaEventDisableTiming);
        cudaFuncSetAttribute(k_mmagemm<false>, cudaFuncAttributeMaxDynamicSharedMemorySize, G_SMEM);
        cudaFuncSetAttribute(k_mmagemm<true>,  cudaFuncAttributeMaxDynamicSharedMemorySize, G_SMEM);
    }

    dim3 g64(NV / 64, NV / 64);
    dim3 gtc(NV / 128, NV / 128);

    // main: init -> gather -> (wait tpass) cost0 -> GEMM1 -> GEMM2 -> finalize
    // side: (wait init) tpass -> (wait gather) cost1 -> d_w -> orth
    k_init<<<128, 256>>>();
    cudaEventRecord(e_init, 0);

    cudaStreamWaitEvent(s_side, e_init, 0);
    k_tpass<<<dim3(NV / 32, NV / 32), dim3(32, 8), 0, s_side>>>(trans);
    cudaEventRecord(e_tpass, s_side);

    k_gather<<<2 * NV, DV>>>(index1, index2, emb1_w, emb2_w);
    cudaEventRecord(e_gather, 0);

    cudaStreamWaitEvent(s_side, e_gather, 0);
    k_cost_mma<true><<<g64, 256, 0, s_side>>>(1, cost2, mu_t);     // Dt + qform
    cudaEventRecord(e_cost1, s_side);
    k_cost_mma<false><<<g64, 256, 0, s_side>>>(0, trans, nullptr); // d_w
    k_orth_part<<<dim3(64, 2), 256, 0, s_side>>>();
    k_orth_fin<<<1, 256, 0, s_side>>>();
    cudaEventRecord(e_side, s_side);

    cudaStreamWaitEvent(0, e_tpass, 0);
    k_cost_mma<true><<<g64, 256>>>(0, cost1, mu_s);                // Ds + qform
    k_mmagemm<false><<<gtc, 256, G_SMEM>>>(trans);                 // X = Ds@T
    cudaStreamWaitEvent(0, e_cost1, 0);
    k_mmagemm<true><<<gtc, 256, G_SMEM>>>(trans);                  // <T, X@Dt>
    cudaStreamWaitEvent(0, e_side, 0);
    k_finalize<<<1, 256>>>(out);
}